// round 12
// baseline (speedup 1.0000x reference)
#include <cuda_runtime.h>
#include <cuda_bf16.h>
#include <cstdint>

typedef unsigned long long ull;

// ---------------------------------------------------------------------------
// Scratch (bf16 hi/lo-split GEMM operands, K=48 per row = 96 B)
//   g_A[m][48]: [Phi(16) | Phi(16) | Plo(16)]
//   g_W[v][48]: [Whi(16) | Wlo(16) | Whi(16)]
// D = Phi*Whi + Phi*Wlo + Plo*Whi (+ bias in epilogue); lo*lo term ~2^-18
// ---------------------------------------------------------------------------
__device__ __align__(16) __nv_bfloat16 g_A[4096 * 48];
__device__ __align__(16) __nv_bfloat16 g_W[32000 * 48];

__device__ __forceinline__ uint32_t smem_u32(const void* p) {
    uint32_t a;
    asm("{ .reg .u64 t; cvta.to.shared.u64 t, %1; cvt.u32.u64 %0, t; }"
        : "=r"(a) : "l"(p));
    return a;
}
__device__ __forceinline__ void bf16_split(float x, __nv_bfloat16& hi, __nv_bfloat16& lo) {
    hi = __float2bfloat16(x);
    lo = __float2bfloat16(x - __bfloat162float(hi));
}

// ---------------------------------------------------------------------------
// Kernel 1 (fused): blocks [0, prepBlocks): half-warp-per-token circuit -> g_A
//                   blocks [prepBlocks, ...): W_out conversion        -> g_W
// ---------------------------------------------------------------------------
__global__ __launch_bounds__(256)
void prep_all_kernel(const int* __restrict__ ids,
                     const int* __restrict__ mask,
                     const float* __restrict__ We,
                     const float* __restrict__ gates,
                     const float* __restrict__ Wout,
                     int BS, int depth, int S, int B, int V, int prepBlocks) {
    if (blockIdx.x < (unsigned)prepBlocks) {
        __shared__ float sgt[2 * 256];   // transposed: sgt[l*256 + d*16 + o]
        for (int i = threadIdx.x; i < depth * 256; i += 256) {
            int l = i >> 8, r = i & 255, o = r >> 4, d = r & 15;
            sgt[l * 256 + d * 16 + o] = gates[i];
        }
        __syncthreads();

        int lane = threadIdx.x & 31, wid = threadIdx.x >> 5;
        int half = lane >> 4, k = lane & 15;
        int m = blockIdx.x * 16 + wid * 2 + half;
        if (m >= BS) return;

        int tok = ids[m];
        float e = We[(size_t)tok * 16 + k];
        float s = e * e;
#pragma unroll
        for (int off = 8; off; off >>= 1)
            s += __shfl_xor_sync(0xffffffffu, s, off, 16);
        e *= 1.f / (sqrtf(s) + 1e-12f);
        float st = e;

        for (int l = 0; l < depth; l++) {
            float acc = 0.f;
            const float* g = sgt + l * 256 + k;
#pragma unroll
            for (int d = 0; d < 16; d++) {
                float sd = __shfl_sync(0xffffffffu, st, d, 16);
                acc = fmaf(sd, g[d * 16], acc);
            }
            float x = acc * (0.99f * 0.99f) + (0.01f / 16.f);
            float s2 = x * x;
#pragma unroll
            for (int off = 8; off; off >>= 1)
                s2 += __shfl_xor_sync(0xffffffffu, s2, off, 16);
            st = x * (1.f / (sqrtf(s2) + 1e-12f));
        }
        st = st * 0.99f + (0.01f / 16.f);

        int s_pos = m % S;
        bool ap = true;
        for (int b = 0; b < B; b++) ap = ap && (mask[b * S + s_pos] != 0);

        float v = ap ? st : e;
        __nv_bfloat16 hi, lo; bf16_split(v, hi, lo);
        __nv_bfloat16* row = g_A + (size_t)m * 48;
        row[k] = hi; row[16 + k] = hi; row[32 + k] = lo;
    } else {
        int v = (blockIdx.x - prepBlocks) * 256 + threadIdx.x;
        if (v >= V) return;
        const float* wr = Wout + (size_t)v * 16;
        __nv_bfloat16* row = g_W + (size_t)v * 48;
#pragma unroll
        for (int k = 0; k < 16; k++) {
            __nv_bfloat16 hi, lo; bf16_split(wr[k], hi, lo);
            row[k] = hi; row[16 + k] = lo; row[32 + k] = hi;
        }
    }
}

// ---------------------------------------------------------------------------
// Kernel 2: HMMA bf16 GEMM, tile 128x256, 512 threads / 16 warps (4x4).
// Warp tile 32 rows x 64 cols. K=48 (3 k-steps). B fragments via ldmatrix.x4
// (2 nt tiles per instruction). Per output element vs R11: A-side LDG/STS/
// ldmatrix halves, B ldmatrix instruction count halves. smem row stride 56
// bf16 (112B): r*112 mod 128 spans 8 distinct 16B groups -> ldmatrix
// conflict-free. Bias from smem; shuffle-paired float4 stores (proven R10).
// ---------------------------------------------------------------------------
#define SA 56   // smem row stride in bf16

__global__ __launch_bounds__(512)
void hmma_gemm_kernel(const float* __restrict__ bout,
                      float* __restrict__ out, int V) {
    __shared__ __align__(16) __nv_bfloat16 sA[128 * SA];   // 14336 B
    __shared__ __align__(16) __nv_bfloat16 sB[256 * SA];   // 28672 B
    __shared__ __align__(16) float s_bias[256];            //  1024 B

    int tid = threadIdx.x, wid = tid >> 5, lane = tid & 31;
    int row0 = blockIdx.y * 128;
    int v0   = blockIdx.x * 256;

    // cooperative tile loads: A 768 uint4, B 1536 uint4
    {
        const uint4* srcA = (const uint4*)(g_A + (size_t)row0 * 48);
#pragma unroll
        for (int i = tid; i < 768; i += 512) {
            int r = i / 6, c = i % 6;
            *(uint4*)(sA + r * SA + c * 8) = srcA[i];
        }
        const uint4* srcB = (const uint4*)(g_W + (size_t)v0 * 48);
#pragma unroll
        for (int i = tid; i < 1536; i += 512) {
            int r = i / 6, c = i % 6;
            *(uint4*)(sB + r * SA + c * 8) = srcB[i];
        }
        if (tid < 64) ((float4*)s_bias)[tid] = ((const float4*)(bout + v0))[tid];
    }
    __syncthreads();

    int wm = wid >> 2;        // 0..3 : 32-row quarter
    int wn = wid & 3;         // 0..3 : 64-col quarter

    // ldmatrix lane->address mapping
    int aRowL = (lane & 7) + ((lane >> 3) & 1) * 8;
    int aColH = ((lane >> 4) & 1) * 8;
    // B .x4: lane group g=lane>>3: tile-in-pair = g>>1, k-half = g&1
    int g8   = lane >> 3;
    int bRow = (g8 >> 1) * 8 + (lane & 7);
    int bColH = (g8 & 1) * 8;

    uint32_t aBase = smem_u32(sA);
    uint32_t bBase = smem_u32(sB);

    float c[2][8][4];
#pragma unroll
    for (int mt = 0; mt < 2; mt++)
#pragma unroll
        for (int nt = 0; nt < 8; nt++)
#pragma unroll
            for (int j = 0; j < 4; j++) c[mt][nt][j] = 0.f;

#pragma unroll
    for (int k = 0; k < 3; k++) {
        uint32_t a[2][4], b[4][4];
#pragma unroll
        for (int mt = 0; mt < 2; mt++) {
            uint32_t addr = aBase +
                (uint32_t)(((wm * 32 + mt * 16 + aRowL) * SA + k * 16 + aColH) * 2);
            asm volatile("ldmatrix.sync.aligned.m8n8.x4.shared.b16 {%0,%1,%2,%3}, [%4];"
                         : "=r"(a[mt][0]), "=r"(a[mt][1]), "=r"(a[mt][2]), "=r"(a[mt][3])
                         : "r"(addr));
        }
#pragma unroll
        for (int np = 0; np < 4; np++) {   // nt pair: tiles 2np, 2np+1
            uint32_t addr = bBase +
                (uint32_t)(((wn * 64 + np * 16 + bRow) * SA + k * 16 + bColH) * 2);
            asm volatile("ldmatrix.sync.aligned.m8n8.x4.shared.b16 {%0,%1,%2,%3}, [%4];"
                         : "=r"(b[np][0]), "=r"(b[np][1]), "=r"(b[np][2]), "=r"(b[np][3])
                         : "r"(addr));
        }
#pragma unroll
        for (int mt = 0; mt < 2; mt++)
#pragma unroll
            for (int np = 0; np < 4; np++) {
                asm volatile(
                    "mma.sync.aligned.m16n8k16.row.col.f32.bf16.bf16.f32 "
                    "{%0,%1,%2,%3}, {%4,%5,%6,%7}, {%8,%9}, {%0,%1,%2,%3};"
                    : "+f"(c[mt][2*np][0]), "+f"(c[mt][2*np][1]),
                      "+f"(c[mt][2*np][2]), "+f"(c[mt][2*np][3])
                    : "r"(a[mt][0]), "r"(a[mt][1]), "r"(a[mt][2]), "r"(a[mt][3]),
                      "r"(b[np][0]), "r"(b[np][1]));
                asm volatile(
                    "mma.sync.aligned.m16n8k16.row.col.f32.bf16.bf16.f32 "
                    "{%0,%1,%2,%3}, {%4,%5,%6,%7}, {%8,%9}, {%0,%1,%2,%3};"
                    : "+f"(c[mt][2*np+1][0]), "+f"(c[mt][2*np+1][1]),
                      "+f"(c[mt][2*np+1][2]), "+f"(c[mt][2*np+1][3])
                    : "r"(a[mt][0]), "r"(a[mt][1]), "r"(a[mt][2]), "r"(a[mt][3]),
                      "r"(b[np][2]), "r"(b[np][3]));
            }
    }

    // bias add (per original column ownership, before the shuffle exchange)
    int rr = lane >> 2;
    int q2 = (lane & 3) * 2;
#pragma unroll
    for (int nt = 0; nt < 8; nt++) {
        float2 bv = *(const float2*)(s_bias + wn * 64 + nt * 8 + q2);
#pragma unroll
        for (int mt = 0; mt < 2; mt++) {
            c[mt][nt][0] += bv.x; c[mt][nt][1] += bv.y;
            c[mt][nt][2] += bv.x; c[mt][nt][3] += bv.y;
        }
    }

    // ---------------- shuffle-paired epilogue (R10) --------------------------
    bool evn = ((lane & 1) == 0);
#pragma unroll
    for (int mt = 0; mt < 2; mt++) {
#pragma unroll
        for (int ntp = 0; ntp < 4; ntp++) {
#pragma unroll
            for (int h2 = 0; h2 < 2; h2++) {
                float a0 = c[mt][2*ntp][h2*2],   a1 = c[mt][2*ntp][h2*2+1];
                float b0 = c[mt][2*ntp+1][h2*2], b1 = c[mt][2*ntp+1][h2*2+1];
                float ra0 = __shfl_xor_sync(0xffffffffu, a0, 1);
                float ra1 = __shfl_xor_sync(0xffffffffu, a1, 1);
                float rb0 = __shfl_xor_sync(0xffffffffu, b0, 1);
                float rb1 = __shfl_xor_sync(0xffffffffu, b1, 1);
                float4 f4;
                int colbase;
                if (evn) {
                    f4 = make_float4(a0, a1, ra0, ra1);
                    colbase = 16 * ntp + q2;
                } else {
                    f4 = make_float4(rb0, rb1, b0, b1);
                    colbase = 16 * ntp + 8 + (q2 - 2);
                }
                int grow = row0 + wm * 32 + mt * 16 + rr + h2 * 8;
                int gcol = v0 + wn * 64 + colbase;
                __stcs((float4*)(out + (size_t)grow * V + gcol), f4);
            }
        }
    }
}

// ---------------------------------------------------------------------------
// Launch
// ---------------------------------------------------------------------------
extern "C" void kernel_launch(void* const* d_in, const int* in_sizes, int n_in,
                              void* d_out, int out_size) {
    const int*   ids   = (const int*)d_in[0];
    const int*   mask  = (const int*)d_in[1];
    const float* We    = (const float*)d_in[2];
    const float* gates = (const float*)d_in[3];
    const float* Wout  = (const float*)d_in[4];
    const float* bout  = (const float*)d_in[5];
    float* out = (float*)d_out;

    int BS    = in_sizes[0];          // 4096
    int V     = in_sizes[5];          // 32000
    int depth = in_sizes[3] / 256;    // 2
    int S     = 2048;
    int B     = BS / S;

    int prepBlocks  = (BS + 15) / 16;           // 256 (16 tokens per block)
    int wconvBlocks = (V + 255) / 256;          // 125
    prep_all_kernel<<<prepBlocks + wconvBlocks, 256>>>(
        ids, mask, We, gates, Wout, BS, depth, S, B, V, prepBlocks);

    dim3 grid(V / 256, BS / 128);     // (125, 32)
    hmma_gemm_kernel<<<grid, 512>>>(bout, out, V);
}